// round 9
// baseline (speedup 1.0000x reference)
#include <cuda_runtime.h>
#include <cuda_fp16.h>
#include <cstdint>

#define N_ 32
#define C_ 16
#define H_ 256
#define W_ 256
#define HW_ (H_ * W_)
#define CHW_ (C_ * H_ * W_)
#define P_ 2000000

// 64 MB NHWC fp16 scratch: one 32B texel (16 halves) per (n,h,w), 32B-aligned
// so each texel is exactly one 256-bit LDG/STG. Fits in GB300's ~126MB L2.
struct __align__(32) Texel8 { uint32_t u[8]; };
__device__ Texel8 g_tex[(size_t)N_ * HW_];

__device__ __forceinline__ uint32_t pack_h2(float a, float b) {
    __half2 h = __floats2half2_rn(a, b);
    return *reinterpret_cast<uint32_t*>(&h);
}

// 256-bit texel load, L2 evict-last (keep scratch resident in L2).
__device__ __forceinline__ void ld_texel(const Texel8* p, uint32_t r[8]) {
    asm volatile("ld.global.nc.L2::evict_last.v8.u32 {%0,%1,%2,%3,%4,%5,%6,%7}, [%8];"
                 : "=r"(r[0]), "=r"(r[1]), "=r"(r[2]), "=r"(r[3]),
                   "=r"(r[4]), "=r"(r[5]), "=r"(r[6]), "=r"(r[7])
                 : "l"(p));
}

// 256-bit texel store, L2 evict-last.
__device__ __forceinline__ void st_texel(Texel8* p, const uint32_t r[8]) {
    asm volatile("st.global.L2::evict_last.v8.u32 [%0], {%1,%2,%3,%4,%5,%6,%7,%8};"
                 :: "l"(p), "r"(r[0]), "r"(r[1]), "r"(r[2]), "r"(r[3]),
                    "r"(r[4]), "r"(r[5]), "r"(r[6]), "r"(r[7]) : "memory");
}

// NCHW fp32 -> NHWC fp16. One thread per texel: 16 strided evict-first reads
// (warp-coalesced 128B per channel), one 32B v8 store (warp: 1KB contiguous).
__global__ void __launch_bounds__(256) transpose_to_nhwc_h(const float* __restrict__ in) {
    int idx = blockIdx.x * blockDim.x + threadIdx.x;   // texel: n*HW + h*W + w
    if (idx >= N_ * HW_) return;
    int n  = idx >> 16;
    int hw = idx & (HW_ - 1);
    const float* src = in + (size_t)n * CHW_ + hw;
    float v[C_];
#pragma unroll
    for (int c = 0; c < C_; c++) v[c] = __ldcs(src + c * HW_);

    uint32_t r[8];
#pragma unroll
    for (int j = 0; j < 8; j++) r[j] = pack_h2(v[2 * j], v[2 * j + 1]);
    st_texel(&g_tex[idx], r);
}

// ONE thread per point: 4 corners x one 256-bit texel load, fp32
// weights/accumulation, 64B coalesced streaming output.
__global__ void __launch_bounds__(256) gather_bilinear_h(
    const float2* __restrict__ grid,
    const int* __restrict__ indices,
    float* __restrict__ out)
{
    int p = blockIdx.x * blockDim.x + threadIdx.x;
    if (p >= P_) return;

    float2 g = __ldcs(grid + p);
    float x = (g.x + 1.0f) * 0.5f * (float)(W_ - 1);
    float y = (g.y + 1.0f) * 0.5f * (float)(H_ - 1);
    float x0f = floorf(x);
    float y0f = floorf(y);
    float wx = x - x0f;
    float wy = y - y0f;
    int x0 = (int)x0f, y0 = (int)y0f;
    int x1 = x0 + 1,   y1 = y0 + 1;

    bool vx0 = (x0 >= 0) & (x0 <= W_ - 1);
    bool vx1 = (x1 >= 0) & (x1 <= W_ - 1);
    bool vy0 = (y0 >= 0) & (y0 <= H_ - 1);
    bool vy1 = (y1 >= 0) & (y1 <= H_ - 1);

    int x0c = min(max(x0, 0), W_ - 1);
    int x1c = min(max(x1, 0), W_ - 1);
    int y0c = min(max(y0, 0), H_ - 1);
    int y1c = min(max(y1, 0), H_ - 1);

    float w00 = (1.0f - wx) * (1.0f - wy) * (float)(vx0 && vy0);
    float w01 = wx * (1.0f - wy) * (float)(vx1 && vy0);
    float w10 = (1.0f - wx) * wy * (float)(vx0 && vy1);
    float w11 = wx * wy * (float)(vx1 && vy1);

    int n = __ldcs(indices + p) & (N_ - 1);
    const Texel8* base = g_tex + (size_t)n * HW_;

    uint32_t r00[8], r01[8], r10[8], r11[8];
    ld_texel(base + y0c * W_ + x0c, r00);
    ld_texel(base + y0c * W_ + x1c, r01);
    ld_texel(base + y1c * W_ + x0c, r10);
    ld_texel(base + y1c * W_ + x1c, r11);

    float acc[C_];
#pragma unroll
    for (int j = 0; j < 8; j++) {
        float2 f00 = __half22float2(*reinterpret_cast<__half2*>(&r00[j]));
        float2 f01 = __half22float2(*reinterpret_cast<__half2*>(&r01[j]));
        float2 f10 = __half22float2(*reinterpret_cast<__half2*>(&r10[j]));
        float2 f11 = __half22float2(*reinterpret_cast<__half2*>(&r11[j]));
        acc[2*j+0] = w00 * f00.x + w01 * f01.x + w10 * f10.x + w11 * f11.x;
        acc[2*j+1] = w00 * f00.y + w01 * f01.y + w10 * f10.y + w11 * f11.y;
    }

    float4* o = reinterpret_cast<float4*>(out) + (size_t)p * 4;
#pragma unroll
    for (int i = 0; i < 4; i++)
        __stcs(o + i, make_float4(acc[4*i+0], acc[4*i+1], acc[4*i+2], acc[4*i+3]));
}

extern "C" void kernel_launch(void* const* d_in, const int* in_sizes, int n_in,
                              void* d_out, int out_size) {
    const float*  input   = (const float*)d_in[0];
    const float2* grid    = (const float2*)d_in[1];
    const int*    indices = (const int*)d_in[2];
    float*        out     = (float*)d_out;

    {
        int total = N_ * HW_;
        int threads = 256;
        int blocks = (total + threads - 1) / threads;
        transpose_to_nhwc_h<<<blocks, threads>>>(input);
    }
    {
        int threads = 256;
        int blocks = (P_ + threads - 1) / threads;
        gather_bilinear_h<<<blocks, threads>>>(grid, indices, out);
    }
}

// round 10
// speedup vs baseline: 1.1621x; 1.1621x over previous
#include <cuda_runtime.h>
#include <cuda_fp16.h>
#include <cstdint>

#define N_ 32
#define C_ 16
#define H_ 256
#define W_ 256
#define HW_ (H_ * W_)
#define CHW_ (C_ * H_ * W_)
#define P_ 2000000

// 64 MB NHWC fp16 scratch: one 32B texel (16 halves) per (n,h,w), 32B-aligned.
// Fits in GB300's ~126 MB L2.
struct __align__(32) Texel8 { uint32_t u[8]; };
__device__ Texel8 g_tex[(size_t)N_ * HW_];

__device__ __forceinline__ uint32_t pack_h2(float a, float b) {
    __half2 h = __floats2half2_rn(a, b);
    return *reinterpret_cast<uint32_t*>(&h);
}

// L2 evict-last policy (createpolicy+cache_hint form works for any width).
__device__ __forceinline__ uint64_t evict_last_policy() {
    uint64_t pol;
    asm("createpolicy.fractional.L2::evict_last.b64 %0, 1.0;" : "=l"(pol));
    return pol;
}

__device__ __forceinline__ uint2 ld_evict_last(const uint2* p, uint64_t pol) {
    uint2 r;
    asm volatile("ld.global.nc.L2::cache_hint.v2.u32 {%0,%1}, [%2], %3;"
                 : "=r"(r.x), "=r"(r.y) : "l"(p), "l"(pol));
    return r;
}

// 256-bit texel store, L2 evict-last (native v8 form).
__device__ __forceinline__ void st_texel(Texel8* p, const uint32_t r[8]) {
    asm volatile("st.global.L2::evict_last.v8.u32 [%0], {%1,%2,%3,%4,%5,%6,%7,%8};"
                 :: "l"(p), "r"(r[0]), "r"(r[1]), "r"(r[2]), "r"(r[3]),
                    "r"(r[4]), "r"(r[5]), "r"(r[6]), "r"(r[7]) : "memory");
}

// NCHW fp32 -> NHWC fp16. One thread per texel: 16 strided evict-first reads
// (warp-coalesced 128B per channel), one 32B v8 evict-last store.
__global__ void __launch_bounds__(256) transpose_to_nhwc_h(const float* __restrict__ in) {
    int idx = blockIdx.x * blockDim.x + threadIdx.x;   // texel: n*HW + h*W + w
    if (idx >= N_ * HW_) return;
    int n  = idx >> 16;
    int hw = idx & (HW_ - 1);
    const float* src = in + (size_t)n * CHW_ + hw;
    float v[C_];
#pragma unroll
    for (int c = 0; c < C_; c++) v[c] = __ldcs(src + c * HW_);

    uint32_t r[8];
#pragma unroll
    for (int j = 0; j < 8; j++) r[j] = pack_h2(v[2 * j], v[2 * j + 1]);
    st_texel(&g_tex[idx], r);
}

// 4 lanes per point, 2 points per lane-group. Lane-chunk i handles channels
// [4i,4i+4) of both points; all 8 corner loads (8B each, evict-last) are
// issued before any consumption -> 8 outstanding loads/thread.
__global__ void __launch_bounds__(256) gather_bilinear_h(
    const float2* __restrict__ grid,
    const int* __restrict__ indices,
    float* __restrict__ out)
{
    int t = blockIdx.x * blockDim.x + threadIdx.x;
    int grp = t >> 2;            // handles points 2*grp, 2*grp+1
    int i   = t & 3;             // channel chunk
    if (grp >= P_ / 2) return;

    // coalesced per-group loads: both grids (16B), both indices (8B)
    float4 g2 = __ldcs(reinterpret_cast<const float4*>(grid) + grp);
    int2   n2 = __ldcs(reinterpret_cast<const int2*>(indices) + grp);

    float w0[2], w1[2], w2[2], w3[2];
    const uint2* addr[2][4];

#pragma unroll
    for (int k = 0; k < 2; k++) {
        float gx = k ? g2.z : g2.x;
        float gy = k ? g2.w : g2.y;
        float x = (gx + 1.0f) * 0.5f * (float)(W_ - 1);
        float y = (gy + 1.0f) * 0.5f * (float)(H_ - 1);
        float x0f = floorf(x);
        float y0f = floorf(y);
        float wx = x - x0f;
        float wy = y - y0f;
        int x0 = (int)x0f, y0 = (int)y0f;
        int x1 = x0 + 1,   y1 = y0 + 1;

        bool vx0 = (x0 >= 0) & (x0 <= W_ - 1);
        bool vx1 = (x1 >= 0) & (x1 <= W_ - 1);
        bool vy0 = (y0 >= 0) & (y0 <= H_ - 1);
        bool vy1 = (y1 >= 0) & (y1 <= H_ - 1);

        int x0c = min(max(x0, 0), W_ - 1);
        int x1c = min(max(x1, 0), W_ - 1);
        int y0c = min(max(y0, 0), H_ - 1);
        int y1c = min(max(y1, 0), H_ - 1);

        w0[k] = (1.0f - wx) * (1.0f - wy) * (float)(vx0 && vy0);
        w1[k] = wx * (1.0f - wy) * (float)(vx1 && vy0);
        w2[k] = (1.0f - wx) * wy * (float)(vx0 && vy1);
        w3[k] = wx * wy * (float)(vx1 && vy1);

        int n = (k ? n2.y : n2.x) & (N_ - 1);
        const uint2* base = reinterpret_cast<const uint2*>(g_tex) + (size_t)n * (HW_ * 4) + i;
        addr[k][0] = base + (y0c * W_ + x0c) * 4;
        addr[k][1] = base + (y0c * W_ + x1c) * 4;
        addr[k][2] = base + (y1c * W_ + x0c) * 4;
        addr[k][3] = base + (y1c * W_ + x1c) * 4;
    }

    uint64_t pol = evict_last_policy();
    uint2 r[2][4];
#pragma unroll
    for (int k = 0; k < 2; k++)
#pragma unroll
        for (int c = 0; c < 4; c++)
            r[k][c] = ld_evict_last(addr[k][c], pol);

#pragma unroll
    for (int k = 0; k < 2; k++) {
        float2 a0 = __half22float2(*reinterpret_cast<__half2*>(&r[k][0].x));
        float2 b0 = __half22float2(*reinterpret_cast<__half2*>(&r[k][0].y));
        float2 a1 = __half22float2(*reinterpret_cast<__half2*>(&r[k][1].x));
        float2 b1 = __half22float2(*reinterpret_cast<__half2*>(&r[k][1].y));
        float2 a2 = __half22float2(*reinterpret_cast<__half2*>(&r[k][2].x));
        float2 b2 = __half22float2(*reinterpret_cast<__half2*>(&r[k][2].y));
        float2 a3 = __half22float2(*reinterpret_cast<__half2*>(&r[k][3].x));
        float2 b3 = __half22float2(*reinterpret_cast<__half2*>(&r[k][3].y));

        float4 res;
        res.x = w0[k] * a0.x + w1[k] * a1.x + w2[k] * a2.x + w3[k] * a3.x;
        res.y = w0[k] * a0.y + w1[k] * a1.y + w2[k] * a2.y + w3[k] * a3.y;
        res.z = w0[k] * b0.x + w1[k] * b1.x + w2[k] * b2.x + w3[k] * b3.x;
        res.w = w0[k] * b0.y + w1[k] * b1.y + w2[k] * b2.y + w3[k] * b3.y;

        __stcs(reinterpret_cast<float4*>(out) + (size_t)(2 * grp + k) * 4 + i, res);
    }
}

extern "C" void kernel_launch(void* const* d_in, const int* in_sizes, int n_in,
                              void* d_out, int out_size) {
    const float*  input   = (const float*)d_in[0];
    const float2* grid    = (const float2*)d_in[1];
    const int*    indices = (const int*)d_in[2];
    float*        out     = (float*)d_out;

    {
        int total = N_ * HW_;
        int threads = 256;
        int blocks = (total + threads - 1) / threads;
        transpose_to_nhwc_h<<<blocks, threads>>>(input);
    }
    {
        long long total = (long long)(P_ / 2) * 4;   // 4 lanes per 2-point group
        int threads = 256;
        int blocks = (int)((total + threads - 1) / threads);
        gather_bilinear_h<<<blocks, threads>>>(grid, indices, out);
    }
}